// round 5
// baseline (speedup 1.0000x reference)
#include <cuda_runtime.h>

#define NBOX   10647          // 52*52*3 + 26*26*3 + 13*13*3
#define NBATCH 4
#define SPTOT  3549           // 52*52 + 26*26 + 13*13
#define NTEAM  (3*NBATCH*SPTOT)
#define DET_ELEMS (NBATCH*NBOX*6)
#define CAP    256            // per-(batch,class) bucket capacity (mean ~66, >20 sigma safe)

#define THREADS 256
#define GRID    ((4*NTEAM + THREADS - 1) / THREADS)   // 666 blocks, all co-resident
#define NMS_BLOCKS (NBATCH*80)                        // 320

// Scratch (__device__ globals — zero-initialized at load; kernel restores zeros each call)
__device__ int   g_cnt[NBATCH*80];
__device__ float g_bucket[NBATCH*80*CAP*8];  // b0,b1,b2,b3 | area,conf,idx,pad
__device__ volatile int g_arrive;
__device__ int   g_done;

__constant__ float c_anch[3][3][2] = {
  {{10.f,13.f},{16.f,30.f},{33.f,23.f}},
  {{30.f,61.f},{62.f,45.f},{59.f,119.f}},
  {{116.f,90.f},{156.f,198.f},{373.f,326.f}}
};

__device__ __forceinline__ float sigmoidf_(float x){ return 1.0f/(1.0f + expf(-x)); }

// Fused decode + device-wide barrier + per-class NMS. 666 blocks x 256 threads;
// __launch_bounds__(256,5) guarantees >=5 blocks/SM (740 capacity > 666), so the
// software barrier is deadlock-free (all blocks resident in wave 1).
__global__ void __launch_bounds__(THREADS, 5)
fused_kernel(const float* __restrict__ f1,
             const float* __restrict__ f2,
             const float* __restrict__ f3,
             float* __restrict__ det_out,
             float* __restrict__ keep_out){
    __shared__ float s_b0[CAP], s_b1[CAP], s_b2[CAP], s_b3[CAP];
    __shared__ float s_area[CAP], s_conf[CAP];
    __shared__ int   s_idx[CAP];

    // ---------------- Phase 1: decode (4 lanes per box) ----------------
    {
        int tid  = blockIdx.x*THREADS + threadIdx.x;
        int team = tid >> 2;
        int sub  = tid & 3;
        bool valid = (team < NTEAM);
        if (team >= NTEAM) team = NTEAM - 1;     // clamp; keep full warps for shfl

        int a = team / (NBATCH*SPTOT);
        int r = team - a*(NBATCH*SPTOT);
        int b = r / SPTOT;
        int s = r - b*SPTOT;

        const float* feat; int H; float stride; int nbase; int si;
        if (s < 2704)      { feat=f1; H=52; stride=8.0f;  nbase=0;     si=0; }
        else if (s < 3380) { s-=2704; feat=f2; H=26; stride=16.0f; nbase=8112;  si=1; }
        else               { s-=3380; feat=f3; H=13; stride=32.0f; nbase=10140; si=2; }

        int HW = H*H;
        int h = s / H, w = s - h*H;
        const float* fc = feat + ((long)b*255 + a*85)*HW + s;

        // Split 80-class argmax: lane sub handles classes sub, sub+4, ..., 76+sub.
        const float* fcls = fc + 5L*HW;
        float best = fcls[(long)sub*HW];
        int   bi   = sub;
        #pragma unroll
        for (int i = 1; i < 20; i++){
            int e = sub + 4*i;
            float v = fcls[(long)e*HW];
            if (v > best){ best = v; bi = e; }
        }
        // Merge: larger value wins; tie -> smaller index (first-occurrence argmax).
        #pragma unroll
        for (int off = 1; off < 4; off <<= 1){
            float ob = __shfl_xor_sync(0xFFFFFFFFu, best, off);
            int   oi = __shfl_xor_sync(0xFFFFFFFFu, bi,   off);
            if (ob > best || (ob == best && oi < bi)){ best = ob; bi = oi; }
        }

        // Box params: lane sub loads channel sub (tx,ty,tw,th); everyone loads tc.
        float va = fc[(long)sub*HW];
        float tc = fc[4L*HW];
        int lbase = (threadIdx.x & 31) & ~3;
        float tx = __shfl_sync(0xFFFFFFFFu, va, lbase+0);
        float ty = __shfl_sync(0xFFFFFFFFu, va, lbase+1);
        float tw = __shfl_sync(0xFFFFFFFFu, va, lbase+2);
        float th = __shfl_sync(0xFFFFFFFFu, va, lbase+3);

        // Reference math, same op order
        float x  = (sigmoidf_(tx) + (float)w) * stride;
        float y  = (sigmoidf_(ty) + (float)h) * stride;
        float bw = expf(tw) * c_anch[si][a][0] * stride;
        float bh = expf(th) * c_anch[si][a][1] * stride;
        float conf = sigmoidf_(tc);

        float b0 = x - bw*0.5f, b1 = x + bw*0.5f;   // both from x (reference quirk)
        float b2 = y - bh*0.5f, b3 = y + bh*0.5f;   // both from y
        float area = fmaxf(b2-b0+1.0f, 0.0f) * fmaxf(b3-b1+1.0f, 0.0f);

        int n = nbase + (w*H + h)*3 + a;            // reference flatten order
        long o = (long)b*NBOX + n;

        if (valid){
            float* dp = det_out + o*6;
            float corner = (sub==0)?b0 : (sub==1)?b1 : (sub==2)?b2 : b3;
            dp[sub] = corner;
            if (sub == 0) dp[4] = conf;
            if (sub == 1) dp[5] = (float)bi;
            if (sub == 2) keep_out[o] = 0.0f;        // NMS overwrites valid boxes

            if (sub == 0 && conf > 0.5f){
                int pos = atomicAdd(&g_cnt[b*80 + bi], 1);
                if (pos < CAP){
                    float4* rec = (float4*)(g_bucket + ((long)(b*80 + bi)*CAP + pos)*8);
                    rec[0] = make_float4(b0, b1, b2, b3);
                    rec[1] = make_float4(area, conf, (float)n, 0.0f);
                }
            }
        }
    }

    // ---------------- Device-wide barrier ----------------
    __threadfence();                                 // publish this thread's stores
    __syncthreads();
    if (threadIdx.x == 0) atomicAdd((int*)&g_arrive, 1);
    if (blockIdx.x >= NMS_BLOCKS) return;            // decode-only blocks exit

    if (threadIdx.x == 0){
        while (g_arrive < GRID) __nanosleep(64);     // spin until all decode done
    }
    __syncthreads();
    __threadfence();                                 // acquire side

    // ---------------- Phase 2: NMS (one bucket per block) ----------------
    int bc = blockIdx.x;                             // b*80 + c
    int b  = bc / 80;
    int t  = threadIdx.x;

    int cnt = g_cnt[bc]; if (cnt > CAP) cnt = CAP;

    const float4* base = (const float4*)(g_bucket + (long)bc*CAP*8);
    for (int i = t; i < cnt; i += THREADS){
        float4 lo = base[2*i], hi = base[2*i+1];
        s_b0[i]=lo.x; s_b1[i]=lo.y; s_b2[i]=lo.z; s_b3[i]=lo.w;
        s_area[i]=hi.x; s_conf[i]=hi.y; s_idx[i]=(int)hi.z;
    }
    __syncthreads();
    if (t == 0) g_cnt[bc] = 0;                       // restore zero for next call

    int warp = t >> 5, lane = t & 31;
    for (int i = warp; i < cnt; i += (THREADS/32)){
        float ib0=s_b0[i], ib1=s_b1[i], ib2=s_b2[i], ib3=s_b3[i];
        float areai=s_area[i], confi=s_conf[i];
        bool found = false;
        for (int j0 = 0; j0 < cnt; j0 += 32){
            int j = j0 + lane;
            bool p = false;
            if (j < cnt && confi < s_conf[j]){       // conf_i < conf_j (skips j==i)
                float wI = fminf(ib2, s_b2[j]) - fmaxf(ib0, s_b0[j]) + 1.0f;
                float hI = fminf(ib3, s_b3[j]) - fmaxf(ib1, s_b1[j]) + 1.0f;
                wI = fmaxf(wI, 0.0f); hI = fmaxf(hI, 0.0f);
                float inter = wI * hI;
                if (inter > 0.0f){                   // inter==0 -> ref iou 0 or NaN -> false
                    float uni = areai + s_area[j] - inter;   // same op order as reference
                    p = inter / uni > 0.4f;          // same IEEE div as reference
                }
            }
            if (__any_sync(0xFFFFFFFFu, p)){ found = true; break; }
        }
        if (lane == 0)
            keep_out[(long)b*NBOX + s_idx[i]] = found ? 1.0f : 0.0f;
    }

    // ---------------- Epilogue: restore barrier counters ----------------
    __syncthreads();
    if (t == 0){
        int d = atomicAdd(&g_done, 1);
        if (d == NMS_BLOCKS - 1){                    // last NMS block: all spinners passed
            g_done = 0;
            *(int*)&g_arrive = 0;
        }
    }
}

extern "C" void kernel_launch(void* const* d_in, const int* in_sizes, int n_in,
                              void* d_out, int out_size){
    const float* f1 = (const float*)d_in[0];   // (4,255,52,52)
    const float* f2 = (const float*)d_in[1];   // (4,255,26,26)
    const float* f3 = (const float*)d_in[2];   // (4,255,13,13)
    float* det  = (float*)d_out;               // (4,10647,6) then keep (4,10647)
    float* keep = det + DET_ELEMS;

    fused_kernel<<<GRID, THREADS>>>(f1, f2, f3, det, keep);
}

// round 6
// speedup vs baseline: 1.1061x; 1.1061x over previous
#include <cuda_runtime.h>
#include <math_constants.h>

#define NBOX   10647          // 52*52*3 + 26*26*3 + 13*13*3
#define NBATCH 4
#define SPTOT  3549           // 52*52 + 26*26 + 13*13
#define NTEAM  (3*NBATCH*SPTOT)
#define DET_ELEMS (NBATCH*NBOX*6)
#define CAP    256            // per-(batch,class) bucket capacity (mean ~66, >20 sigma safe)

// Scratch (__device__ globals — zero-initialized at load; nms re-zeroes g_cnt after use)
__device__ int   g_cnt[NBATCH*80];
__device__ float g_bucket[NBATCH*80*CAP*8];  // b0,b1,b2,b3 | area,conf,idx,pad

__constant__ float c_anch[3][3][2] = {
  {{10.f,13.f},{16.f,30.f},{33.f,23.f}},
  {{30.f,61.f},{62.f,45.f},{59.f,119.f}},
  {{116.f,90.f},{156.f,198.f},{373.f,326.f}}
};

__device__ __forceinline__ float sigmoidf_(float x){ return 1.0f/(1.0f + expf(-x)); }

// 4 lanes per box: each lane scans 20 of 80 classes (stride 4) -> shfl-merge.
__global__ void decode_kernel(const float* __restrict__ f1,
                              const float* __restrict__ f2,
                              const float* __restrict__ f3,
                              float* __restrict__ det_out,
                              float* __restrict__ keep_out){
    int tid  = blockIdx.x*blockDim.x + threadIdx.x;
    int team = tid >> 2;
    int sub  = tid & 3;
    bool valid = (team < NTEAM);
    if (team >= NTEAM) team = NTEAM - 1;        // clamp; keep full warps for shfl

    int a = team / (NBATCH*SPTOT);
    int r = team - a*(NBATCH*SPTOT);
    int b = r / SPTOT;
    int s = r - b*SPTOT;

    const float* feat; int H; float stride; int nbase; int si;
    if (s < 2704)      { feat=f1; H=52; stride=8.0f;  nbase=0;     si=0; }
    else if (s < 3380) { s-=2704; feat=f2; H=26; stride=16.0f; nbase=8112;  si=1; }
    else               { s-=3380; feat=f3; H=13; stride=32.0f; nbase=10140; si=2; }

    int HW = H*H;
    int h = s / H, w = s - h*H;
    const float* fc = feat + ((long)b*255 + a*85)*HW + s;

    // Split 80-class argmax: lane sub handles classes sub, sub+4, ..., 76+sub.
    const float* fcls = fc + 5L*HW;
    float best = fcls[(long)sub*HW];
    int   bi   = sub;
    #pragma unroll
    for (int i = 1; i < 20; i++){
        int e = sub + 4*i;
        float v = fcls[(long)e*HW];
        if (v > best){ best = v; bi = e; }
    }
    // Merge: larger value wins; tie -> smaller index (global first-occurrence argmax).
    #pragma unroll
    for (int off = 1; off < 4; off <<= 1){
        float ob = __shfl_xor_sync(0xFFFFFFFFu, best, off);
        int   oi = __shfl_xor_sync(0xFFFFFFFFu, bi,   off);
        if (ob > best || (ob == best && oi < bi)){ best = ob; bi = oi; }
    }

    // Box params: lane sub loads channel sub (tx,ty,tw,th); everyone loads tc.
    float va = fc[(long)sub*HW];
    float tc = fc[4L*HW];
    int lbase = (threadIdx.x & 31) & ~3;
    float tx = __shfl_sync(0xFFFFFFFFu, va, lbase+0);
    float ty = __shfl_sync(0xFFFFFFFFu, va, lbase+1);
    float tw = __shfl_sync(0xFFFFFFFFu, va, lbase+2);
    float th = __shfl_sync(0xFFFFFFFFu, va, lbase+3);

    // Reference math, same op order
    float x  = (sigmoidf_(tx) + (float)w) * stride;
    float y  = (sigmoidf_(ty) + (float)h) * stride;
    float bw = expf(tw) * c_anch[si][a][0] * stride;
    float bh = expf(th) * c_anch[si][a][1] * stride;
    float conf = sigmoidf_(tc);

    float b0 = x - bw*0.5f, b1 = x + bw*0.5f;   // both from x (reference quirk)
    float b2 = y - bh*0.5f, b3 = y + bh*0.5f;   // both from y
    float area = fmaxf(b2-b0+1.0f, 0.0f) * fmaxf(b3-b1+1.0f, 0.0f);

    int n = nbase + (w*H + h)*3 + a;            // reference flatten order
    long o = (long)b*NBOX + n;

    if (valid){
        float* dp = det_out + o*6;
        float corner = (sub==0)?b0 : (sub==1)?b1 : (sub==2)?b2 : b3;
        dp[sub] = corner;
        if (sub == 0) dp[4] = conf;
        if (sub == 1) dp[5] = (float)bi;
        if (sub == 2) keep_out[o] = 0.0f;        // NMS overwrites valid boxes

        if (sub == 0 && conf > 0.5f){
            int pos = atomicAdd(&g_cnt[b*80 + bi], 1);
            if (pos < CAP){
                float4* rec = (float4*)(g_bucket + ((long)(b*80 + bi)*CAP + pos)*8);
                rec[0] = make_float4(b0, b1, b2, b3);
                rec[1] = make_float4(area, conf, (float)n, 0.0f);
            }
        }
    }
}

// One block per (batch,class) bucket. Vectorized smem records + sentinel padding:
// pad slots get conf=-inf so the conf predicate kills them (no j<cnt check needed).
#define NMS_THREADS 512
__global__ void nms_kernel(float* __restrict__ keep_out){
    __shared__ float4 s_lo[CAP];     // b0,b1,b2,b3
    __shared__ float2 s_ac[CAP];     // area, conf
    __shared__ int    s_idx[CAP];

    int bc = blockIdx.x;                         // b*80 + c
    int b  = bc / 80;
    int t  = threadIdx.x;

    int cnt = g_cnt[bc]; if (cnt > CAP) cnt = CAP;
    int cntPad = (cnt + 31) & ~31;

    const float4* base = (const float4*)(g_bucket + (long)bc*CAP*8);
    for (int i = t; i < cntPad; i += NMS_THREADS){
        if (i < cnt){
            float4 lo = base[2*i], hi = base[2*i+1];
            s_lo[i] = lo;
            s_ac[i] = make_float2(hi.x, hi.y);
            s_idx[i] = (int)hi.z;
        } else {
            s_lo[i] = make_float4(0.f,0.f,0.f,0.f);
            s_ac[i] = make_float2(0.f, -CUDART_INF_F);   // sentinel: conf_i < -inf never
        }
    }
    __syncthreads();
    if (t == 0) g_cnt[bc] = 0;                   // restore zero for next call

    int warp = t >> 5, lane = t & 31;
    for (int i = warp; i < cnt; i += (NMS_THREADS/32)){
        float4 il = s_lo[i];                     // warp-uniform broadcast
        float2 ia = s_ac[i];
        bool found = false;
        for (int j0 = 0; j0 < cntPad; j0 += 32){
            int j = j0 + lane;                   // always in-bounds (padded)
            float4 jl = s_lo[j];                 // one LDS.128
            float2 ja = s_ac[j];                 // one LDS.64
            bool p = (ia.y < ja.y);              // conf_i < conf_j (false on pads & j==i)
            if (p){
                float wI = fminf(il.z, jl.z) - fmaxf(il.x, jl.x) + 1.0f;
                float hI = fminf(il.w, jl.w) - fmaxf(il.y, jl.y) + 1.0f;
                wI = fmaxf(wI, 0.0f); hI = fmaxf(hI, 0.0f);
                float inter = wI * hI;
                p = (inter > 0.0f) &&            // inter==0 -> ref iou 0 or NaN -> false
                    (inter / (ia.x + ja.x - inter) > 0.4f);  // same op order, IEEE div
            }
            if (__any_sync(0xFFFFFFFFu, p)){ found = true; break; }
        }
        if (lane == 0)
            keep_out[(long)b*NBOX + s_idx[i]] = found ? 1.0f : 0.0f;
    }
}

extern "C" void kernel_launch(void* const* d_in, const int* in_sizes, int n_in,
                              void* d_out, int out_size){
    const float* f1 = (const float*)d_in[0];   // (4,255,52,52)
    const float* f2 = (const float*)d_in[1];   // (4,255,26,26)
    const float* f3 = (const float*)d_in[2];   // (4,255,13,13)
    float* det  = (float*)d_out;               // (4,10647,6) then keep (4,10647)
    float* keep = det + DET_ELEMS;

    decode_kernel<<<(4*NTEAM + 127)/128, 128>>>(f1, f2, f3, det, keep);
    nms_kernel   <<<NBATCH*80, NMS_THREADS>>>(keep);
}